// round 5
// baseline (speedup 1.0000x reference)
#include <cuda_runtime.h>
#include <math.h>

#define SEQL  2048
#define BATCH 64
#define INDIM 512
#define HID   512
#define GATES 2048
#define NCTA  128
#define NTHR  256

// kernel A geometry
#define A_ROWS  64
#define A_RP    32
#define A_TLEN  512          // t per CTA (4 t-chunks x 32 row-blocks = 128 CTAs)
#define A_KC    64           // k-chunk (floats)
#define A_NKC   8
#define PWA     1028         // interleaved weight row stride (floats)

// kernel B geometry
#define PADX  516
#define PADW  1028
#define PSP   68

typedef unsigned long long u64;

__device__ float g_P[(size_t)SEQL * GATES * BATCH];   // 1 GiB xproj scratch
__device__ volatile unsigned g_flags[NCTA];           // per-CTA step flags

__device__ __forceinline__ float sigm(float x){ return 1.0f/(1.0f+__expf(-x)); }
__device__ __forceinline__ float ftanh(float x){
    return __fdividef(2.0f, 1.0f + __expf(-2.0f*x)) - 1.0f;
}

__device__ __forceinline__ u64 dup2(float v){
    u64 r; asm("mov.b64 %0, {%1, %2};" : "=l"(r) : "f"(v), "f"(v)); return r;
}
__device__ __forceinline__ void ffma2(u64 &d, u64 a, u64 b){
    asm("fma.rn.f32x2 %0, %1, %2, %0;" : "+l"(d) : "l"(a), "l"(b));
}
__device__ __forceinline__ float2 un2(u64 v){
    float2 f; asm("mov.b64 {%0, %1}, %2;" : "=f"(f.x), "=f"(f.y) : "l"(v)); return f;
}
__device__ __forceinline__ void cp16(unsigned s, const void* g){
    asm volatile("cp.async.cg.shared.global [%0], [%1], 16;" :: "r"(s), "l"(g) : "memory");
}
__device__ __forceinline__ void cp_commit(){ asm volatile("cp.async.commit_group;" ::: "memory"); }
template<int N> __device__ __forceinline__ void cp_wait(){
    asm volatile("cp.async.wait_group %0;" :: "n"(N) : "memory");
}

// ============================ Kernel A: x projection ============================
__global__ void __launch_bounds__(NTHR, 1)
xproj_kernel(const float* __restrict__ input,
             const float* __restrict__ Wih,
             const float* __restrict__ bih,
             const float* __restrict__ bhh)
{
    extern __shared__ float smem[];
    float* xs  = smem;                     // 2 * 64 * 64 (double-buffered x chunk, swizzled)
    float* wsm = xs + 2 * A_KC * BATCH;    // 32 rowpairs * PWA

    const int tid = threadIdx.x;
    const int rb  = blockIdx.x & 31;
    const int tc  = blockIdx.x >> 5;
    const int r0  = rb * A_ROWS;
    const int t0  = tc * A_TLEN;

    // resident Wih slice, interleaved row pairs: wsm[rp][k] = (W[r0+2rp][k], W[r0+2rp+1][k])
    for (int i = tid; i < A_RP * INDIM; i += NTHR) {
        int rp = i >> 9, k = i & 511;
        ((float2*)(wsm + rp * PWA))[k] =
            make_float2(Wih[(size_t)(r0 + 2*rp)   * INDIM + k],
                        Wih[(size_t)(r0 + 2*rp+1) * INDIM + k]);
    }

    const int rq = tid >> 5;               // row-group 0..7 (4 rowpairs each)
    const int bg = tid & 31;
    const int b1 = bg, b2 = bg + 32;
    const int sw = bg & 15;                // x swizzle key (same for b1, b2)

    u64 bias2[4];
#pragma unroll
    for (int j = 0; j < 4; ++j) {
        int row = r0 + (rq*4 + j) * 2;
        float lo = bih[row]   + bhh[row];
        float hi = bih[row+1] + bhh[row+1];
        asm("mov.b64 %0, {%1,%2};" : "=l"(bias2[j]) : "f"(lo), "f"(hi));
    }

    const unsigned sxs = (unsigned)__cvta_generic_to_shared(xs);
    const int sb = tid >> 2;               // staging: b row
    const int su0 = (tid & 3) * 4;         // staging: first 16B unit

    auto issue = [&](int ci){
        int tt = t0 + (ci >> 3);
        int c  = ci & 7;
        const float* src = input + (size_t)tt * BATCH * INDIM
                                 + (size_t)sb * INDIM + c * A_KC + su0 * 4;
        unsigned dst = sxs + (unsigned)(((ci & 1) * (A_KC * BATCH) + sb * A_KC) * 4);
#pragma unroll
        for (int j = 0; j < 4; ++j) {
            int u = su0 + j;
            cp16(dst + (unsigned)(((u ^ (sb & 15)) ) * 16), src + j * 4);
        }
        cp_commit();
    };

    __syncthreads();                       // wsm visible before compute
    issue(0); issue(1);

    const int NCI = A_TLEN * A_NKC;        // 4096

    for (int t = 0; t < A_TLEN; ++t) {
        u64 acc[4][2];
#pragma unroll
        for (int rp = 0; rp < 4; ++rp) { acc[rp][0] = bias2[rp]; acc[rp][1] = bias2[rp]; }

        for (int c = 0; c < A_NKC; ++c) {
            int ci = t * A_NKC + c;
            if (ci == NCI - 1) cp_wait<0>(); else cp_wait<1>();
            __syncthreads();
            const float4* x1p = (const float4*)(xs + (ci & 1) * (A_KC*BATCH) + b1 * A_KC);
            const float4* x2p = (const float4*)(xs + (ci & 1) * (A_KC*BATCH) + b2 * A_KC);
            const float*  wb  = wsm + (rq * 4) * PWA + c * (A_KC * 2);
#pragma unroll
            for (int kk = 0; kk < 16; ++kk) {
                float4 xa = x1p[kk ^ sw];
                float4 xc = x2p[kk ^ sw];
                u64 a0 = dup2(xa.x), a1 = dup2(xa.y), a2 = dup2(xa.z), a3 = dup2(xa.w);
                u64 c0 = dup2(xc.x), c1 = dup2(xc.y), c2 = dup2(xc.z), c3 = dup2(xc.w);
#pragma unroll
                for (int rp = 0; rp < 4; ++rp) {
                    const ulonglong2* wp = ((const ulonglong2*)(wb + rp * PWA)) + kk * 2;
                    ulonglong2 p = wp[0], q = wp[1];
                    ffma2(acc[rp][0], a0, p.x); ffma2(acc[rp][0], a1, p.y);
                    ffma2(acc[rp][0], a2, q.x); ffma2(acc[rp][0], a3, q.y);
                    ffma2(acc[rp][1], c0, p.x); ffma2(acc[rp][1], c1, p.y);
                    ffma2(acc[rp][1], c2, q.x); ffma2(acc[rp][1], c3, q.y);
                }
            }
            __syncthreads();
            if (ci + 2 < NCI) issue(ci + 2);
        }

        size_t tg = (size_t)(t0 + t);
#pragma unroll
        for (int rp = 0; rp < 4; ++rp) {
            int row = r0 + (rq*4 + rp) * 2;
            float2 v0 = un2(acc[rp][0]);
            float2 v1 = un2(acc[rp][1]);
            float* P0 = g_P + (tg * GATES + (size_t)row) * BATCH;
            P0[b1] = v0.x;  P0[BATCH + b1] = v0.y;
            P0[b2] = v1.x;  P0[BATCH + b2] = v1.y;
        }
    }
}

// ============================ Kernel B: recurrence ============================

// stage 64x512 fp32 (b-major) from gmem into padded smem buffer, non-blocking
__device__ __forceinline__ void stage(const float* __restrict__ g, unsigned sbase, int tid){
#pragma unroll
    for (int j = 0; j < 32; ++j){
        int i = tid + j * NTHR;
        int row = i >> 7, c4 = i & 127;
        cp16(sbase + (unsigned)(row * PADX + c4 * 4) * 4u, g + (size_t)i * 4);
    }
    cp_commit();
}

__device__ __forceinline__ void mm(const float4* __restrict__ x0,
                                   const float4* __restrict__ x1,
                                   const ulonglong2* __restrict__ w0,
                                   const ulonglong2* __restrict__ w1,
                                   const ulonglong2* __restrict__ w2,
                                   const ulonglong2* __restrict__ w3,
                                   u64 acc[2][4])
{
#pragma unroll 4
    for (int kk = 0; kk < 32; ++kk){
        float4 a = x0[kk];
        float4 b = x1[kk];
        u64 a0 = dup2(a.x), a1 = dup2(a.y), a2 = dup2(a.z), a3 = dup2(a.w);
        u64 b0 = dup2(b.x), b1 = dup2(b.y), b2 = dup2(b.z), b3 = dup2(b.w);
        {
            ulonglong2 p = w0[kk*2], q = w0[kk*2+1];
            ffma2(acc[0][0], a0, p.x); ffma2(acc[0][0], a1, p.y);
            ffma2(acc[0][0], a2, q.x); ffma2(acc[0][0], a3, q.y);
            ffma2(acc[1][0], b0, p.x); ffma2(acc[1][0], b1, p.y);
            ffma2(acc[1][0], b2, q.x); ffma2(acc[1][0], b3, q.y);
        }
        {
            ulonglong2 p = w1[kk*2], q = w1[kk*2+1];
            ffma2(acc[0][1], a0, p.x); ffma2(acc[0][1], a1, p.y);
            ffma2(acc[0][1], a2, q.x); ffma2(acc[0][1], a3, q.y);
            ffma2(acc[1][1], b0, p.x); ffma2(acc[1][1], b1, p.y);
            ffma2(acc[1][1], b2, q.x); ffma2(acc[1][1], b3, q.y);
        }
        {
            ulonglong2 p = w2[kk*2], q = w2[kk*2+1];
            ffma2(acc[0][2], a0, p.x); ffma2(acc[0][2], a1, p.y);
            ffma2(acc[0][2], a2, q.x); ffma2(acc[0][2], a3, q.y);
            ffma2(acc[1][2], b0, p.x); ffma2(acc[1][2], b1, p.y);
            ffma2(acc[1][2], b2, q.x); ffma2(acc[1][2], b3, q.y);
        }
        {
            ulonglong2 p = w3[kk*2], q = w3[kk*2+1];
            ffma2(acc[0][3], a0, p.x); ffma2(acc[0][3], a1, p.y);
            ffma2(acc[0][3], a2, q.x); ffma2(acc[0][3], a3, q.y);
            ffma2(acc[1][3], b0, p.x); ffma2(acc[1][3], b1, p.y);
            ffma2(acc[1][3], b2, q.x); ffma2(acc[1][3], b3, q.y);
        }
    }
}

__global__ void __launch_bounds__(NTHR, 1)
lstm_rec(const float* __restrict__ Whh, float* __restrict__ out)
{
    extern __shared__ float smem[];
    float* buf  = smem;                         // 64 * PADX (h_{t-1})
    float* whh  = buf  + BATCH * PADX;          // 8 * PADW (interleaved hcl pairs)
    float* part = whh  + 8 * PADW;              // 4096
    float* ps   = part + 4096;                  // 2 * 16 * PSP (P slice, double buf)
    float* sF0  = ps   + 2 * 16 * PSP;          // 1

    const int tid = threadIdx.x;
    const int cta = blockIdx.x;
    const int hc0 = cta * 4;

    if (tid == 0) *((unsigned*)sF0) = g_flags[cta];   // common epoch base

    const unsigned sbuf = (unsigned)__cvta_generic_to_shared(buf);
    const unsigned sps  = (unsigned)__cvta_generic_to_shared(ps);

    // resident Whh slice, interleaved hcl pairs
    for (int i = tid; i < 8 * HID; i += NTHR) {
        int r = i >> 9, k = i & 511;
        int g = r >> 1, hp = r & 1;
        int row0 = g * HID + hc0 + hp * 2;
        ((float2*)(whh + r * PADW))[k] =
            make_float2(Whh[(size_t)row0 * HID + k], Whh[(size_t)(row0+1) * HID + k]);
    }

    // P-slice prefetch identity
    const int prl = tid >> 4, pu = tid & 15;
    const int pgrow = (prl >> 2) * HID + hc0 + (prl & 3);

    // prefetch ps(0)
    cp16(sps + (unsigned)((prl * PSP + pu * 4) * 4),
         g_P + ((size_t)0 * GATES + (size_t)pgrow) * BATCH + pu * 4);
    cp_commit();

    // mm decomposition: warp = (K-quarter, batch-half); lane = (hp, bsub, bg)
    const int q     = tid >> 6;
    const int bhalf = (tid >> 5) & 1;
    const int l     = tid & 31;
    const int bg    = l & 7;
    const int bsub  = (l >> 3) & 1;
    const int hp    = l >> 4;
    const int brow  = bhalf * 32 + bsub * 16 + bg;

    const float4* x0 = ((const float4*)(buf + brow * PADX)) + q * 32;
    const float4* x1 = x0 + (8 * PADX) / 4;
    const ulonglong2* wh0 = ((const ulonglong2*)(whh + (0*2+hp) * PADW)) + q * 64;
    const ulonglong2* wh1 = ((const ulonglong2*)(whh + (1*2+hp) * PADW)) + q * 64;
    const ulonglong2* wh2 = ((const ulonglong2*)(whh + (2*2+hp) * PADW)) + q * 64;
    const ulonglong2* wh3 = ((const ulonglong2*)(whh + (3*2+hp) * PADW)) + q * 64;

    float2* p2 = (float2*)part;

    // update identity: one (b, hcl) per thread
    const int ub   = tid >> 2;
    const int uhcl = tid & 3;
    const int uhp  = uhcl >> 1;
    const int uc   = uhcl & 1;
    const float* pbase = part + (ub * 16 + uhp * 2 + uc);

    float cst = 0.0f;

    __syncthreads();
    const unsigned F0 = *((unsigned*)sF0);

    for (int t = 0; t < SEQL; ++t) {
        u64 acc[2][4];
#pragma unroll
        for (int i = 0; i < 2; ++i)
#pragma unroll
            for (int g = 0; g < 4; ++g) acc[i][g] = 0ull;

        if (t > 0) {
            if (tid < 32) {                  // warp 0 polls all 128 flags
                unsigned tgt = F0 + (unsigned)t;
                for (;;) {
                    unsigned f0 = g_flags[tid];
                    unsigned f1 = g_flags[tid + 32];
                    unsigned f2 = g_flags[tid + 64];
                    unsigned f3 = g_flags[tid + 96];
                    bool ok = ((int)(f0 - tgt) >= 0) & ((int)(f1 - tgt) >= 0)
                            & ((int)(f2 - tgt) >= 0) & ((int)(f3 - tgt) >= 0);
                    if (__all_sync(0xffffffffu, ok)) break;
                }
                __threadfence();
            }
            __syncthreads();
            stage(out + (size_t)(t - 1) * BATCH * HID, sbuf, tid);
            cp_wait<0>();
            __syncthreads();
            mm(x0, x1, wh0, wh1, wh2, wh3, acc);
        }

        // K-split partials: [q][b*8 + g*2 + hp] as float2 over the hcl pair
#pragma unroll
        for (int bb = 0; bb < 2; ++bb) {
            int b = brow + bb * 8;
#pragma unroll
            for (int g = 0; g < 4; ++g)
                p2[q * 512 + b * 8 + g * 2 + hp] = un2(acc[bb][g]);
        }
        if (t == 0) cp_wait<0>();            // ps(0)
        __syncthreads();

        // prefetch ps(t+1) — lands during update/barrier of this step
        if (t + 1 < SEQL) {
            cp16(sps + (unsigned)((((t+1) & 1) * 16 * PSP + prl * PSP + pu * 4) * 4),
                 g_P + ((size_t)(t+1) * GATES + (size_t)pgrow) * BATCH + pu * 4);
            cp_commit();
        }

        // gate update
        {
            const float* psb = ps + (t & 1) * 16 * PSP;
            float sv[4];
#pragma unroll
            for (int g = 0; g < 4; ++g) {
                float s = psb[(g * 4 + uhcl) * PSP + ub];
#pragma unroll
                for (int qq = 0; qq < 4; ++qq)
                    s += pbase[qq * 1024 + g * 4];
                sv[g] = s;
            }
            float ig = sigm(sv[0]);
            float fg = sigm(sv[1]);
            float gv = ftanh(sv[2]);
            float og = sigm(sv[3]);
            float cn = fmaf(fg, cst, ig * gv);
            cst = cn;
            float hn = og * ftanh(cn);
            out[(size_t)t * BATCH * HID + (size_t)ub * HID + hc0 + uhcl] = hn;
            if (t == SEQL - 1)
                out[(size_t)SEQL * BATCH * HID + (size_t)ub * HID + hc0 + uhcl] = hn;
        }
        __threadfence();
        __syncthreads();
        if (tid == 0) g_flags[cta] = F0 + (unsigned)(t + 1);
    }

    // c_n
    out[(size_t)SEQL * BATCH * HID + (size_t)BATCH * HID
        + (size_t)ub * HID + hc0 + uhcl] = cst;
}

extern "C" void kernel_launch(void* const* d_in, const int* in_sizes, int n_in,
                              void* d_out, int out_size)
{
    const float* input = (const float*)d_in[0];
    const float* Wih   = (const float*)d_in[1];
    const float* Whh   = (const float*)d_in[2];
    const float* bih   = (const float*)d_in[3];
    const float* bhh   = (const float*)d_in[4];
    float* out = (float*)d_out;

    size_t smemA = (size_t)(2 * A_KC * BATCH + A_RP * PWA) * sizeof(float);
    size_t smemB = (size_t)(BATCH * PADX + 8 * PADW + 4096 + 2 * 16 * PSP + 4) * sizeof(float);

    static int configured = 0;
    if (!configured) {
        cudaFuncSetAttribute(xproj_kernel,
                             cudaFuncAttributeMaxDynamicSharedMemorySize, (int)smemA);
        cudaFuncSetAttribute(lstm_rec,
                             cudaFuncAttributeMaxDynamicSharedMemorySize, (int)smemB);
        configured = 1;
    }

    xproj_kernel<<<NCTA, NTHR, smemA>>>(input, Wih, bih, bhh);
    lstm_rec<<<NCTA, NTHR, smemB>>>(Whh, out);
}

// round 7
// speedup vs baseline: 1.4499x; 1.4499x over previous
#include <cuda_runtime.h>
#include <math.h>

#define SEQL  2048
#define BATCH 64
#define INDIM 512
#define HID   512
#define NCTA  128
#define NTHR  256
#define PADX  516            // activation buffer row stride (floats)
#define PADW  1028           // interleaved weight row stride (floats)

typedef unsigned long long u64;

__device__ unsigned g_flags[NCTA];      // per-CTA step flags (monotonic across runs)

__device__ __forceinline__ float sigm(float x){ return 1.0f/(1.0f+__expf(-x)); }

// ---- packed fp32x2 (SASS FFMA2) ----
__device__ __forceinline__ u64 dup2(float v){
    u64 r; asm("mov.b64 %0, {%1, %2};" : "=l"(r) : "f"(v), "f"(v)); return r;
}
__device__ __forceinline__ void ffma2(u64 &d, u64 a, u64 b){
    asm("fma.rn.f32x2 %0, %1, %2, %0;" : "+l"(d) : "l"(a), "l"(b));
}
__device__ __forceinline__ float2 un2(u64 v){
    float2 f; asm("mov.b64 {%0, %1}, %2;" : "=f"(f.x), "=f"(f.y) : "l"(v)); return f;
}

// ---- cp.async ----
__device__ __forceinline__ void cp16(unsigned s, const void* g){
    asm volatile("cp.async.cg.shared.global [%0], [%1], 16;" :: "r"(s), "l"(g) : "memory");
}
__device__ __forceinline__ void cp_commit(){ asm volatile("cp.async.commit_group;" ::: "memory"); }
template<int N> __device__ __forceinline__ void cp_wait(){
    asm volatile("cp.async.wait_group %0;" :: "n"(N) : "memory");
}

// ---- release/acquire flag ops ----
__device__ __forceinline__ void st_rel(unsigned* p, unsigned v){
    asm volatile("st.release.gpu.u32 [%0], %1;" :: "l"(p), "r"(v) : "memory");
}
__device__ __forceinline__ unsigned ld_acq(unsigned* p){
    unsigned v; asm volatile("ld.acquire.gpu.u32 %0, [%1];" : "=r"(v) : "l"(p) : "memory");
    return v;
}

// stage full 64x512 fp32 (b-major, contiguous) into padded smem buffer
__device__ __forceinline__ void stage_full(const float* __restrict__ g, unsigned sbase, int tid){
#pragma unroll
    for (int j = 0; j < 32; ++j){
        int i = tid + j * NTHR;
        int row = i >> 7, c4 = i & 127;
        cp16(sbase + (unsigned)(row * PADX + c4 * 4) * 4u, g + (size_t)i * 4);
    }
    cp_commit();
}

// stage one 256-column half of 64x512 fp32
__device__ __forceinline__ void stage_half(const float* __restrict__ g, unsigned sbase,
                                           int tid, int hf){
#pragma unroll
    for (int j = 0; j < 16; ++j){
        int i = tid + j * NTHR;                 // 0..4095
        int row = i >> 6, c4 = i & 63;
        cp16(sbase + (unsigned)((row * PADX + hf * 256 + c4 * 4) * 4),
             g + (size_t)row * HID + hf * 256 + c4 * 4);
    }
    cp_commit();
}

// 64-k slice of gates += act @ W^T for 2 batches x 4 gates x (hcl pair)
__device__ __forceinline__ void mm16(const float4* __restrict__ x0,
                                     const float4* __restrict__ x1,
                                     const ulonglong2* __restrict__ w0,
                                     const ulonglong2* __restrict__ w1,
                                     const ulonglong2* __restrict__ w2,
                                     const ulonglong2* __restrict__ w3,
                                     u64 acc[2][4])
{
#pragma unroll
    for (int kk = 0; kk < 16; ++kk){
        float4 a = x0[kk];
        float4 b = x1[kk];
        u64 a0 = dup2(a.x), a1 = dup2(a.y), a2 = dup2(a.z), a3 = dup2(a.w);
        u64 b0 = dup2(b.x), b1 = dup2(b.y), b2 = dup2(b.z), b3 = dup2(b.w);
        {
            ulonglong2 p = w0[kk*2], q = w0[kk*2+1];
            ffma2(acc[0][0], a0, p.x); ffma2(acc[0][0], a1, p.y);
            ffma2(acc[0][0], a2, q.x); ffma2(acc[0][0], a3, q.y);
            ffma2(acc[1][0], b0, p.x); ffma2(acc[1][0], b1, p.y);
            ffma2(acc[1][0], b2, q.x); ffma2(acc[1][0], b3, q.y);
        }
        {
            ulonglong2 p = w1[kk*2], q = w1[kk*2+1];
            ffma2(acc[0][1], a0, p.x); ffma2(acc[0][1], a1, p.y);
            ffma2(acc[0][1], a2, q.x); ffma2(acc[0][1], a3, q.y);
            ffma2(acc[1][1], b0, p.x); ffma2(acc[1][1], b1, p.y);
            ffma2(acc[1][1], b2, q.x); ffma2(acc[1][1], b3, q.y);
        }
        {
            ulonglong2 p = w2[kk*2], q = w2[kk*2+1];
            ffma2(acc[0][2], a0, p.x); ffma2(acc[0][2], a1, p.y);
            ffma2(acc[0][2], a2, q.x); ffma2(acc[0][2], a3, q.y);
            ffma2(acc[1][2], b0, p.x); ffma2(acc[1][2], b1, p.y);
            ffma2(acc[1][2], b2, q.x); ffma2(acc[1][2], b3, q.y);
        }
        {
            ulonglong2 p = w3[kk*2], q = w3[kk*2+1];
            ffma2(acc[0][3], a0, p.x); ffma2(acc[0][3], a1, p.y);
            ffma2(acc[0][3], a2, q.x); ffma2(acc[0][3], a3, q.y);
            ffma2(acc[1][3], b0, p.x); ffma2(acc[1][3], b1, p.y);
            ffma2(acc[1][3], b2, q.x); ffma2(acc[1][3], b3, q.y);
        }
    }
}

__global__ void __launch_bounds__(NTHR, 1)
lstm_persistent(const float* __restrict__ input,
                const float* __restrict__ Wih,
                const float* __restrict__ Whh,
                const float* __restrict__ bih,
                const float* __restrict__ bhh,
                float* __restrict__ out)
{
    extern __shared__ float smem[];
    float* buf  = smem;                         // 64 * PADX (x_t, then h_{t-1}, by halves)
    float* wih  = buf  + BATCH * PADX;          // 8 * PADW
    float* whh  = wih  + 8 * PADW;              // 8 * PADW
    float* part = whh  + 8 * PADW;              // 4096
    float* bias = part + 4096;                  // 16
    float* sF0  = bias + 16;                    // 1

    const int tid = threadIdx.x;
    const int cta = blockIdx.x;
    const int hc0 = cta * 4;

    if (tid == 0) *((unsigned*)sF0) = g_flags[cta];

    const unsigned sbuf = (unsigned)__cvta_generic_to_shared(buf);

    // resident weights, interleaved hcl pairs: row r=g*2+hp holds (W[g,2hp],W[g,2hp+1]) per k
    for (int i = tid; i < 8 * 512; i += NTHR) {
        int r = i >> 9, k = i & 511;
        int g = r >> 1, hp = r & 1;
        int row0 = g * HID + hc0 + hp * 2;
        ((float2*)(wih + r * PADW))[k] =
            make_float2(Wih[(size_t)row0 * INDIM + k], Wih[(size_t)(row0+1) * INDIM + k]);
        ((float2*)(whh + r * PADW))[k] =
            make_float2(Whh[(size_t)row0 * HID + k], Whh[(size_t)(row0+1) * HID + k]);
    }
    if (tid < 16) {
        int g = tid >> 2, hcl = tid & 3;
        int grow = g * HID + hc0 + hcl;
        bias[tid] = bih[grow] + bhh[grow];
    }

    // decomposition: warp = (64k-slice q, batch-half); lane = (hp, bsub, bg)
    const int q     = tid >> 6;                 // k-quarter within each 256-half
    const int bhalf = (tid >> 5) & 1;
    const int l     = tid & 31;
    const int bg    = l & 7;
    const int bsub  = (l >> 3) & 1;
    const int hp    = l >> 4;
    const int brow  = bhalf * 32 + bsub * 16 + bg;

    const float4* xq = ((const float4*)(buf + brow * PADX)) + q * 16;  // +hf*64 for half B
    const int XO = (8 * PADX) / 4;              // +8 batches

    const ulonglong2* wi0 = ((const ulonglong2*)(wih + (0*2+hp) * PADW)) + q * 32;
    const ulonglong2* wi1 = ((const ulonglong2*)(wih + (1*2+hp) * PADW)) + q * 32;
    const ulonglong2* wi2 = ((const ulonglong2*)(wih + (2*2+hp) * PADW)) + q * 32;
    const ulonglong2* wi3 = ((const ulonglong2*)(wih + (3*2+hp) * PADW)) + q * 32;
    const ulonglong2* wh0 = ((const ulonglong2*)(whh + (0*2+hp) * PADW)) + q * 32;
    const ulonglong2* wh1 = ((const ulonglong2*)(whh + (1*2+hp) * PADW)) + q * 32;
    const ulonglong2* wh2 = ((const ulonglong2*)(whh + (2*2+hp) * PADW)) + q * 32;
    const ulonglong2* wh3 = ((const ulonglong2*)(whh + (3*2+hp) * PADW)) + q * 32;

    float2* p2 = (float2*)part;

    // update identity: one (b, hcl) output per thread
    const int ub   = tid >> 2;
    const int uhcl = tid & 3;
    const int uhp  = uhcl >> 1;
    const int uc   = uhcl & 1;
    const float* pbase = part + (ub * 16 + uhp * 2 + uc);

    float cst = 0.0f;

    stage_full(input, sbuf, tid);               // prefetch x_0

    __syncthreads();                            // sF0 visible
    const unsigned F0 = *((unsigned*)sF0);

    for (int t = 0; t < SEQL; ++t) {
        cp_wait<0>(); __syncthreads();          // x_t staged (weights on t=0 via LDG/STS+bar)

        u64 acc[2][4];
#pragma unroll
        for (int i = 0; i < 2; ++i)
#pragma unroll
            for (int g = 0; g < 4; ++g) acc[i][g] = 0ull;

        // ---- x-GEMM half A ----
        mm16(xq, xq + XO, wi0, wi1, wi2, wi3, acc);

        // ---- barrier poll (warp 0) while others idle briefly ----
        if (t > 0) {
            if (tid < 32) {
                unsigned tgt = F0 + (unsigned)t;
                for (;;) {
                    unsigned f0 = ld_acq(&g_flags[tid]);
                    unsigned f1 = ld_acq(&g_flags[tid + 32]);
                    unsigned f2 = ld_acq(&g_flags[tid + 64]);
                    unsigned f3 = ld_acq(&g_flags[tid + 96]);
                    bool ok = ((int)(f0 - tgt) >= 0) & ((int)(f1 - tgt) >= 0)
                            & ((int)(f2 - tgt) >= 0) & ((int)(f3 - tgt) >= 0);
                    if (__all_sync(0xffffffffu, ok)) break;
                }
            }
        }
        __syncthreads();                        // all warps past x-half-A reads

        const float* hsrc = out + (size_t)(t - 1) * BATCH * HID;
        if (t > 0) stage_half(hsrc, sbuf, tid, 0);     // hA in flight...

        // ---- x-GEMM half B (covers hA latency) ----
        mm16(xq + 64, xq + 64 + XO, wi0 + 128, wi1 + 128, wi2 + 128, wi3 + 128, acc);
        __syncthreads();                        // all warps done reading buf half B

        if (t > 0) {
            stage_half(hsrc, sbuf, tid, 1);     // hB in flight...
            cp_wait<1>(); __syncthreads();      // hA landed
            mm16(xq, xq + XO, wh0, wh1, wh2, wh3, acc);          // h half A (covers hB)
            cp_wait<0>(); __syncthreads();      // hB landed
            mm16(xq + 64, xq + 64 + XO, wh0 + 128, wh1 + 128, wh2 + 128, wh3 + 128, acc);
        }

        // ---- K-split partials: [q][b*8 + g*2 + hp] as float2 over hcl pair ----
#pragma unroll
        for (int bb = 0; bb < 2; ++bb) {
            int b = brow + bb * 8;
#pragma unroll
            for (int g = 0; g < 4; ++g)
                p2[q * 512 + b * 8 + g * 2 + hp] = un2(acc[bb][g]);
        }
        __syncthreads();                        // partials ready; buf fully dead

        // ---- prefetch x_{t+1}: overlaps update + release ----
        if (t + 1 < SEQL)
            stage_full(input + (size_t)(t + 1) * BATCH * INDIM, sbuf, tid);

        // ---- gate update: one (b, hcl) per thread ----
        {
            float sv[4];
#pragma unroll
            for (int g = 0; g < 4; ++g) {
                float s = bias[g * 4 + uhcl];
#pragma unroll
                for (int qq = 0; qq < 4; ++qq)
                    s += pbase[qq * 1024 + g * 4];
                sv[g] = s;
            }
            float ig = sigm(sv[0]);
            float fg = sigm(sv[1]);
            float gv = tanhf(sv[2]);
            float og = sigm(sv[3]);
            float cn = fmaf(fg, cst, ig * gv);
            cst = cn;
            float hn = og * tanhf(cn);
            out[(size_t)t * BATCH * HID + (size_t)ub * HID + hc0 + uhcl] = hn;
            if (t == SEQL - 1)
                out[(size_t)SEQL * BATCH * HID + (size_t)ub * HID + hc0 + uhcl] = hn;
        }

        // ---- release: h_t stores -> bar -> single release store ----
        __syncthreads();
        if (tid == 0) st_rel(&g_flags[cta], F0 + (unsigned)(t + 1));
    }

    // c_n
    out[(size_t)SEQL * BATCH * HID + (size_t)BATCH * HID
        + (size_t)ub * HID + hc0 + uhcl] = cst;
}

extern "C" void kernel_launch(void* const* d_in, const int* in_sizes, int n_in,
                              void* d_out, int out_size)
{
    const float* input = (const float*)d_in[0];
    const float* Wih   = (const float*)d_in[1];
    const float* Whh   = (const float*)d_in[2];
    const float* bih   = (const float*)d_in[3];
    const float* bhh   = (const float*)d_in[4];
    float* out = (float*)d_out;

    size_t smem = (size_t)(BATCH * PADX + 2 * 8 * PADW + 4096 + 16 + 4) * sizeof(float);
    cudaFuncSetAttribute(lstm_persistent,
                         cudaFuncAttributeMaxDynamicSharedMemorySize, (int)smem);
    lstm_persistent<<<NCTA, NTHR, smem>>>(input, Wih, Whh, bih, bhh, out);
}

// round 8
// speedup vs baseline: 1.6222x; 1.1188x over previous
#include <cuda_runtime.h>
#include <math.h>

#define SEQL  2048
#define BATCH 64
#define INDIM 512
#define HID   512
#define NCTA  128
#define NTHR  512

typedef unsigned long long u64;

__device__ unsigned g_flags[NCTA];      // per-CTA step flags (monotonic across runs)

__device__ __forceinline__ float sigm(float x){ return 1.0f/(1.0f+__expf(-x)); }

// ---- packed fp32x2 (SASS FFMA2) ----
__device__ __forceinline__ u64 dup2(float v){
    u64 r; asm("mov.b64 %0, {%1, %2};" : "=l"(r) : "f"(v), "f"(v)); return r;
}
__device__ __forceinline__ void ffma2(u64 &d, u64 a, u64 b){
    asm("fma.rn.f32x2 %0, %1, %2, %0;" : "+l"(d) : "l"(a), "l"(b));
}
__device__ __forceinline__ float2 un2(u64 v){
    float2 f; asm("mov.b64 {%0, %1}, %2;" : "=f"(f.x), "=f"(f.y) : "l"(v)); return f;
}

// ---- cp.async ----
__device__ __forceinline__ void cp16(unsigned s, const void* g){
    asm volatile("cp.async.cg.shared.global [%0], [%1], 16;" :: "r"(s), "l"(g) : "memory");
}
__device__ __forceinline__ void cp_commit(){ asm volatile("cp.async.commit_group;" ::: "memory"); }
template<int N> __device__ __forceinline__ void cp_wait(){
    asm volatile("cp.async.wait_group %0;" :: "n"(N) : "memory");
}

// ---- release/acquire flags ----
__device__ __forceinline__ void st_rel(unsigned* p, unsigned v){
    asm volatile("st.release.gpu.u32 [%0], %1;" :: "l"(p), "r"(v) : "memory");
}
__device__ __forceinline__ unsigned ld_acq(unsigned* p){
    unsigned v; asm volatile("ld.acquire.gpu.u32 %0, [%1];" : "=r"(v) : "l"(p) : "memory");
    return v;
}

// XOR swizzle key for activation rows (PADX==512, rows bank-aligned otherwise)
__device__ __forceinline__ int xkey(int r){ return (r & 7) | ((r >> 1) & 8); }

// stage full 64x512 fp32 into swizzled smem buffer (all 512 threads)
__device__ __forceinline__ void stage_full(const float* __restrict__ g, unsigned sbase, int tid){
#pragma unroll
    for (int j = 0; j < 16; ++j){
        int i = tid + j * NTHR;                 // chunk index 0..8191
        int row = i >> 7, c4 = i & 127;
        int pos = c4 ^ xkey(row);
        cp16(sbase + (unsigned)((row * 512 + pos * 4) * 4), g + (size_t)i * 4);
    }
    cp_commit();
}

// stage full by 256 threads (warps 8-15), tid2 = tid-256
__device__ __forceinline__ void stage_full256(const float* __restrict__ g, unsigned sbase, int tid2){
#pragma unroll
    for (int j = 0; j < 32; ++j){
        int i = tid2 + j * 256;
        int row = i >> 7, c4 = i & 127;
        int pos = c4 ^ xkey(row);
        cp16(sbase + (unsigned)((row * 512 + pos * 4) * 4), g + (size_t)i * 4);
    }
    cp_commit();
}

// stage one 256-col half of 64x512 fp32 (all 512 threads)
__device__ __forceinline__ void stage_half(const float* __restrict__ g, unsigned sbase,
                                           int tid, int hf){
#pragma unroll
    for (int j = 0; j < 8; ++j){
        int i = tid + j * NTHR;                 // 0..4095
        int row = i >> 6, c = i & 63;
        int pos = (hf * 64 + c) ^ xkey(row);
        cp16(sbase + (unsigned)((row * 512 + pos * 4) * 4),
             g + (size_t)row * HID + hf * 256 + c * 4);
    }
    cp_commit();
}

// 32-k slice of gates += act @ W^T : 2 batches x 4 gates x (hcl pair, packed)
__device__ __forceinline__ void mm8(const float4* __restrict__ xr0,
                                    const float4* __restrict__ xr1,
                                    int cb, int key0, int key1,
                                    const float* __restrict__ w,
                                    int hp, int kb,
                                    u64 acc[2][4])
{
#pragma unroll
    for (int kk = 0; kk < 8; ++kk){
        float4 a = xr0[(cb + kk) ^ key0];
        float4 b = xr1[(cb + kk) ^ key1];
        u64 a0 = dup2(a.x), a1 = dup2(a.y), a2 = dup2(a.z), a3 = dup2(a.w);
        u64 b0 = dup2(b.x), b1 = dup2(b.y), b2 = dup2(b.z), b3 = dup2(b.w);
#pragma unroll
        for (int g = 0; g < 4; ++g){
            const ulonglong2* wg = ((const ulonglong2*)(w + (g * 2 + hp) * 1024)) + kb + kk * 2;
            ulonglong2 p = wg[0], q2 = wg[1];
            ffma2(acc[0][g], a0, p.x);  ffma2(acc[0][g], a1, p.y);
            ffma2(acc[0][g], a2, q2.x); ffma2(acc[0][g], a3, q2.y);
            ffma2(acc[1][g], b0, p.x);  ffma2(acc[1][g], b1, p.y);
            ffma2(acc[1][g], b2, q2.x); ffma2(acc[1][g], b3, q2.y);
        }
    }
}

__global__ void __launch_bounds__(NTHR, 1)
lstm_persistent(const float* __restrict__ input,
                const float* __restrict__ Wih,
                const float* __restrict__ Whh,
                const float* __restrict__ bih,
                const float* __restrict__ bhh,
                float* __restrict__ out)
{
    extern __shared__ float smem[];
    float* buf  = smem;                         // 64 * 512 (swizzled x_t / h_{t-1})
    float* wih  = buf  + BATCH * 512;           // 8 * 1024 (interleaved hcl pairs)
    float* whh  = wih  + 8 * 1024;              // 8 * 1024
    float* part = whh  + 8 * 1024;              // 8 * 1024 (8 K-slices of float2 partials)
    float* bias = part + 8 * 1024;              // 16
    float* sF0  = bias + 16;                    // 1

    const int tid = threadIdx.x;
    const int cta = blockIdx.x;
    const int hc0 = cta * 4;

    if (tid == 0) *((unsigned*)sF0) = g_flags[cta];

    const unsigned sbuf = (unsigned)__cvta_generic_to_shared(buf);

    // resident weights: row r=g*2+hp holds float2(W[g,2hp],W[g,2hp+1]) per k
    for (int i = tid; i < 8 * 512; i += NTHR) {
        int r = i >> 9, k = i & 511;
        int g = r >> 1, hp = r & 1;
        int row0 = g * HID + hc0 + hp * 2;
        ((float2*)(wih + r * 1024))[k] =
            make_float2(Wih[(size_t)row0 * INDIM + k], Wih[(size_t)(row0+1) * INDIM + k]);
        ((float2*)(whh + r * 1024))[k] =
            make_float2(Whh[(size_t)row0 * HID + k], Whh[(size_t)(row0+1) * HID + k]);
    }
    if (tid < 16) {
        int g = tid >> 2, hcl = tid & 3;
        int grow = g * HID + hc0 + hcl;
        bias[tid] = bih[grow] + bhh[grow];
    }

    // decomposition: warp = (q 0..7, bhalf); lane = (hp, bsub, bg)
    const int q     = tid >> 6;
    const int bhalf = (tid >> 5) & 1;
    const int l     = tid & 31;
    const int bg    = l & 7;
    const int bsub  = (l >> 3) & 1;
    const int hp    = l >> 4;
    const int brow  = bhalf * 32 + bsub * 16 + bg;

    const float4* xr0 = (const float4*)(buf + brow * 512);
    const float4* xr1 = (const float4*)(buf + (brow + 8) * 512);
    const int key0 = xkey(brow);
    const int key1 = xkey(brow + 8);
    const int cbA = q * 8;            // chunk base, half A
    const int cbB = 64 + q * 8;       // half B
    const int kbA = q * 16;           // ulonglong2 base, half A
    const int kbB = 128 + q * 16;

    float2* p2 = (float2*)part;

    // update identity (threads 0..255): one (b, hcl) output per thread
    const int ub   = tid >> 2;
    const int uhcl = tid & 3;
    const int uhp  = uhcl >> 1;
    const int uc   = uhcl & 1;
    const float* pbase = part + ((tid >> 2) * 16 + uhp * 2 + uc);

    float cst = 0.0f;

    stage_full(input, sbuf, tid);               // prefetch x_0

    __syncthreads();
    const unsigned F0 = *((unsigned*)sF0);

    for (int t = 0; t < SEQL; ++t) {
        cp_wait<0>(); __syncthreads();          // x_t staged

        u64 acc[2][4];
#pragma unroll
        for (int i = 0; i < 2; ++i)
#pragma unroll
            for (int g = 0; g < 4; ++g) acc[i][g] = 0ull;

        // x-GEMM half A
        mm8(xr0, xr1, cbA, key0, key1, wih, hp, kbA, acc);

        // grid-barrier poll (warp 0)
        if (t > 0 && tid < 32) {
            unsigned tgt = F0 + (unsigned)t;
            for (;;) {
                unsigned f0 = ld_acq(&g_flags[tid]);
                unsigned f1 = ld_acq(&g_flags[tid + 32]);
                unsigned f2 = ld_acq(&g_flags[tid + 64]);
                unsigned f3 = ld_acq(&g_flags[tid + 96]);
                bool ok = ((int)(f0 - tgt) >= 0) & ((int)(f1 - tgt) >= 0)
                        & ((int)(f2 - tgt) >= 0) & ((int)(f3 - tgt) >= 0);
                if (__all_sync(0xffffffffu, ok)) break;
            }
        }
        __syncthreads();                        // barrier seen + xA reads done

        const float* hsrc = out + (size_t)(t - 1) * BATCH * HID;
        if (t > 0) stage_half(hsrc, sbuf, tid, 0);      // hA in flight

        // x-GEMM half B (covers hA latency)
        mm8(xr0, xr1, cbB, key0, key1, wih, hp, kbB, acc);
        __syncthreads();                        // xB reads done

        if (t > 0) {
            stage_half(hsrc, sbuf, tid, 1);     // hB in flight
            cp_wait<1>(); __syncthreads();      // hA landed
            mm8(xr0, xr1, cbA, key0, key1, whh, hp, kbA, acc);   // h half A (covers hB)
            cp_wait<0>(); __syncthreads();      // hB landed
            mm8(xr0, xr1, cbB, key0, key1, whh, hp, kbB, acc);   // h half B
        }

        // K-split partials: [q][b*8 + g*2 + hp] float2 over hcl pair
#pragma unroll
        for (int bb = 0; bb < 2; ++bb) {
            int b = brow + bb * 8;
#pragma unroll
            for (int g = 0; g < 4; ++g)
                p2[q * 512 + b * 8 + g * 2 + hp] = un2(acc[bb][g]);
        }
        __syncthreads();                        // partials ready; buf dead

        if (tid < 256) {
            // gate update: one (b, hcl) per thread
            float sv[4];
#pragma unroll
            for (int g = 0; g < 4; ++g) {
                float s = bias[g * 4 + uhcl];
#pragma unroll
                for (int qq = 0; qq < 8; ++qq)
                    s += pbase[qq * 1024 + g * 4];
                sv[g] = s;
            }
            float ig = sigm(sv[0]);
            float fg = sigm(sv[1]);
            float gv = tanhf(sv[2]);
            float og = sigm(sv[3]);
            float cn = fmaf(fg, cst, ig * gv);
            cst = cn;
            float hn = og * tanhf(cn);
            out[(size_t)t * BATCH * HID + (size_t)ub * HID + hc0 + uhcl] = hn;
            if (t == SEQL - 1)
                out[(size_t)SEQL * BATCH * HID + (size_t)ub * HID + hc0 + uhcl] = hn;

            asm volatile("bar.sync 1, 256;" ::: "memory");     // updaters' h stores done
            if (tid == 0) st_rel(&g_flags[cta], F0 + (unsigned)(t + 1));
        } else {
            // warps 8-15: prefetch x_{t+1} concurrently with update/release
            if (t + 1 < SEQL)
                stage_full256(input + (size_t)(t + 1) * BATCH * INDIM, sbuf, tid - 256);
        }
    }

    // c_n
    if (tid < 256)
        out[(size_t)SEQL * BATCH * HID + (size_t)BATCH * HID
            + (size_t)ub * HID + hc0 + uhcl] = cst;
}

extern "C" void kernel_launch(void* const* d_in, const int* in_sizes, int n_in,
                              void* d_out, int out_size)
{
    const float* input = (const float*)d_in[0];
    const float* Wih   = (const float*)d_in[1];
    const float* Whh   = (const float*)d_in[2];
    const float* bih   = (const float*)d_in[3];
    const float* bhh   = (const float*)d_in[4];
    float* out = (float*)d_out;

    size_t smem = (size_t)(BATCH * 512 + 8 * 1024 * 3 + 16 + 4) * sizeof(float);
    cudaFuncSetAttribute(lstm_persistent,
                         cudaFuncAttributeMaxDynamicSharedMemorySize, (int)smem);
    lstm_persistent<<<NCTA, NTHR, smem>>>(input, Wih, Whh, bih, bhh, out);
}

// round 9
// speedup vs baseline: 2.6296x; 1.6210x over previous
#include <cuda_runtime.h>
#include <cuda_bf16.h>
#include <math.h>

#define SEQL   2048
#define BATCH  64
#define INDIM  512
#define HID    512
#define NCTA   128
#define NTHR   512

#define APITCH 520                 // bf16 elems per activation/weight row
#define AROWB  1040                // bytes per row
#define ACT_COMP 66560             // 64 * 1040 (one split component)
#define ACT_BYTES 133120           // hi + lo
#define WREG   16640               // 16 * 1040 (one weight component)

// smem offsets (bytes)
#define ACT_OFF  0
#define W_OFF    133120            // 4 regions: (Wih,hi)(Wih,lo)(Whh,hi)(Whh,lo)
#define P_OFF    199680            // float part[2][64][18]
#define BIAS_OFF 208896            // 16 floats
#define F0_OFF   208960
#define SMEM_TOTAL 208972

__device__ unsigned g_flags[NCTA];                                   // monotonic across runs
__device__ __align__(16) __nv_bfloat16 g_xs[(size_t)SEQL * 2 * BATCH * APITCH];
__device__ __align__(16) __nv_bfloat16 g_hs[2][2 * BATCH * APITCH];  // ping-pong split h

__device__ __forceinline__ float sigm(float x){ return 1.0f/(1.0f+__expf(-x)); }

// ---- cp.async ----
__device__ __forceinline__ void cp16(unsigned s, const void* g){
    asm volatile("cp.async.cg.shared.global [%0], [%1], 16;" :: "r"(s), "l"(g) : "memory");
}
__device__ __forceinline__ void cp_commit(){ asm volatile("cp.async.commit_group;" ::: "memory"); }
template<int N> __device__ __forceinline__ void cp_wait(){
    asm volatile("cp.async.wait_group %0;" :: "n"(N) : "memory");
}

// ---- release/acquire flags ----
__device__ __forceinline__ void st_rel(unsigned* p, unsigned v){
    asm volatile("st.release.gpu.u32 [%0], %1;" :: "l"(p), "r"(v) : "memory");
}
__device__ __forceinline__ unsigned ld_acq(unsigned* p){
    unsigned v; asm volatile("ld.acquire.gpu.u32 %0, [%1];" : "=r"(v) : "l"(p) : "memory");
    return v;
}

// ---- tensor-core primitives ----
__device__ __forceinline__ void ldsm4(unsigned a, unsigned &r0, unsigned &r1,
                                      unsigned &r2, unsigned &r3){
    asm volatile("ldmatrix.sync.aligned.m8n8.x4.shared.b16 {%0,%1,%2,%3}, [%4];"
                 : "=r"(r0), "=r"(r1), "=r"(r2), "=r"(r3) : "r"(a));
}
__device__ __forceinline__ void ldsm2(unsigned a, unsigned &r0, unsigned &r1){
    asm volatile("ldmatrix.sync.aligned.m8n8.x2.shared.b16 {%0,%1}, [%2];"
                 : "=r"(r0), "=r"(r1) : "r"(a));
}
__device__ __forceinline__ void mmabf(float &c0, float &c1, float &c2, float &c3,
                                      unsigned a0, unsigned a1, unsigned a2, unsigned a3,
                                      unsigned b0, unsigned b1){
    asm volatile("mma.sync.aligned.m16n8k16.row.col.f32.bf16.bf16.f32 "
                 "{%0,%1,%2,%3}, {%4,%5,%6,%7}, {%8,%9}, {%0,%1,%2,%3};"
                 : "+f"(c0), "+f"(c1), "+f"(c2), "+f"(c3)
                 : "r"(a0), "r"(a1), "r"(a2), "r"(a3), "r"(b0), "r"(b1));
}

// ============ conversion kernel: input fp32 -> split bf16 tiles ============
__global__ void __launch_bounds__(256, 4)
xconv(const float* __restrict__ in)
{
    int t = blockIdx.x;
    const float2* src = (const float2*)(in + (size_t)t * BATCH * INDIM);
    __nv_bfloat16* dhi = g_xs + (size_t)t * 2 * BATCH * APITCH;
    __nv_bfloat16* dlo = dhi + BATCH * APITCH;
    for (int i = threadIdx.x; i < BATCH * INDIM / 2; i += 256) {
        int b = i >> 8, kk = i & 255;
        float2 v = src[(size_t)b * 256 + kk];
        __nv_bfloat16 h0 = __float2bfloat16(v.x);
        __nv_bfloat16 h1 = __float2bfloat16(v.y);
        __nv_bfloat162 hp; hp.x = h0; hp.y = h1;
        __nv_bfloat162 lp;
        lp.x = __float2bfloat16(v.x - __bfloat162float(h0));
        lp.y = __float2bfloat16(v.y - __bfloat162float(h1));
        ((__nv_bfloat162*)(dhi + b * APITCH))[kk] = hp;
        ((__nv_bfloat162*)(dlo + b * APITCH))[kk] = lp;
    }
}

// ============ persistent LSTM kernel ============
__global__ void __launch_bounds__(NTHR, 1)
lstm_persistent(const float* __restrict__ Wih,
                const float* __restrict__ Whh,
                const float* __restrict__ bih,
                const float* __restrict__ bhh,
                float* __restrict__ out)
{
    extern __shared__ char smem[];
    const unsigned sbase = (unsigned)__cvta_generic_to_shared(smem);
    const unsigned sact  = sbase + ACT_OFF;
    const unsigned swb   = sbase + W_OFF;
    float* part = (float*)(smem + P_OFF);           // [2][64][18]
    float* bias = (float*)(smem + BIAS_OFF);        // 16
    unsigned* sF0 = (unsigned*)(smem + F0_OFF);

    const int tid = threadIdx.x;
    const int cta = blockIdx.x;
    const int hc0 = cta * 4;

    if (tid == 0) *sF0 = g_flags[cta];

    // ---- convert this CTA's weight slices to split bf16 in smem ----
    for (int i = tid; i < 16 * 512; i += NTHR) {
        int r = i >> 9, k = i & 511;
        int grow = (r >> 2) * HID + hc0 + (r & 3);
        float wv = Wih[(size_t)grow * INDIM + k];
        __nv_bfloat16 h = __float2bfloat16(wv);
        *(__nv_bfloat16*)(smem + W_OFF + 0*WREG + r*AROWB + k*2) = h;
        *(__nv_bfloat16*)(smem + W_OFF + 1*WREG + r*AROWB + k*2) =
            __float2bfloat16(wv - __bfloat162float(h));
        wv = Whh[(size_t)grow * HID + k];
        h = __float2bfloat16(wv);
        *(__nv_bfloat16*)(smem + W_OFF + 2*WREG + r*AROWB + k*2) = h;
        *(__nv_bfloat16*)(smem + W_OFF + 3*WREG + r*AROWB + k*2) =
            __float2bfloat16(wv - __bfloat162float(h));
    }
    if (tid < 16) {
        int grow = (tid >> 2) * HID + hc0 + (tid & 3);
        bias[tid] = bih[grow] + bhh[grow];
    }

    // ---- MMA warp identity: 16 warps = mt(4) x nt(2) x kh(2) ----
    const int wid  = tid >> 5;
    const int lane = tid & 31;
    const int mt   = wid & 3;
    const int nt   = (wid >> 2) & 1;
    const int kh   = (wid >> 3) & 1;
    const int kb   = kh * 256;                       // k offset (elems)

    const int arow = mt * 16 + (lane & 15);
    const int acol = (lane >> 4) * 8;
    const unsigned aAhi = sact + (unsigned)(arow * AROWB + (kb + acol) * 2);
    const unsigned aAlo = aAhi + ACT_COMP;

    const int brow = nt * 8 + (lane & 7);
    const int bcol = ((lane >> 3) & 1) * 8;
    const unsigned bOff = (unsigned)(brow * AROWB + (kb + bcol) * 2);
    const unsigned aBih_hi = swb + 0*WREG + bOff;
    const unsigned aBih_lo = swb + 1*WREG + bOff;
    const unsigned aBhh_hi = swb + 2*WREG + bOff;
    const unsigned aBhh_lo = swb + 3*WREG + bOff;

    // partial store position
    const int prow = mt * 16 + (lane >> 2);
    const int pcol = nt * 8 + (lane & 3) * 2;
    float* pp = part + (size_t)((kh * 64 + prow) * 18 + pcol);

    // update identity (threads 0..255): one (b, hcl) output per thread
    const int ub   = tid >> 2;
    const int uhcl = tid & 3;

    float cst = 0.0f;

    // ---- prefetch x̂_0 ----
    {
        const char* gx0 = (const char*)g_xs;
        for (int i = tid; i < ACT_BYTES / 16; i += NTHR)
            cp16(sact + (unsigned)(i * 16), gx0 + (size_t)i * 16);
        cp_commit();
    }
    __syncthreads();
    const unsigned F0 = *sF0;

    for (int t = 0; t < SEQL; ++t) {
        cp_wait<0>(); __syncthreads();               // x̂_t staged

        float c0 = 0.f, c1 = 0.f, c2 = 0.f, c3 = 0.f;
        unsigned ah0,ah1,ah2,ah3, al0,al1,al2,al3, bh0,bh1, bl0,bl1;

        // ---- x-GEMM chunks 0..7 ----
#pragma unroll 4
        for (int kc = 0; kc < 8; ++kc) {
            unsigned off = kc * 32;
            ldsm4(aAhi + off, ah0,ah1,ah2,ah3);
            ldsm4(aAlo + off, al0,al1,al2,al3);
            ldsm2(aBih_hi + off, bh0,bh1);
            ldsm2(aBih_lo + off, bl0,bl1);
            mmabf(c0,c1,c2,c3, ah0,ah1,ah2,ah3, bh0,bh1);
            mmabf(c0,c1,c2,c3, al0,al1,al2,al3, bh0,bh1);
            mmabf(c0,c1,c2,c3, ah0,ah1,ah2,ah3, bl0,bl1);
        }

        // ---- grid-barrier poll (warp 0) overlapped with other warps' chunks ----
        if (t > 0 && tid < 32) {
            unsigned tgt = F0 + (unsigned)t;
            for (;;) {
                unsigned f0 = ld_acq(&g_flags[tid]);
                unsigned f1 = ld_acq(&g_flags[tid + 32]);
                unsigned f2 = ld_acq(&g_flags[tid + 64]);
                unsigned f3 = ld_acq(&g_flags[tid + 96]);
                bool ok = ((int)(f0 - tgt) >= 0) & ((int)(f1 - tgt) >= 0)
                        & ((int)(f2 - tgt) >= 0) & ((int)(f3 - tgt) >= 0);
                if (__all_sync(0xffffffffu, ok)) break;
            }
        }

        // ---- x-GEMM chunks 8..15 ----
#pragma unroll 4
        for (int kc = 8; kc < 16; ++kc) {
            unsigned off = kc * 32;
            ldsm4(aAhi + off, ah0,ah1,ah2,ah3);
            ldsm4(aAlo + off, al0,al1,al2,al3);
            ldsm2(aBih_hi + off, bh0,bh1);
            ldsm2(aBih_lo + off, bl0,bl1);
            mmabf(c0,c1,c2,c3, ah0,ah1,ah2,ah3, bh0,bh1);
            mmabf(c0,c1,c2,c3, al0,al1,al2,al3, bh0,bh1);
            mmabf(c0,c1,c2,c3, ah0,ah1,ah2,ah3, bl0,bl1);
        }
        __syncthreads();                             // x-MMA done; poll propagated

        if (t > 0) {
            // ---- stage ĥ_{t-1}: hi then lo, separate groups ----
            const char* hs = (const char*)g_hs[(t - 1) & 1];
            for (int i = tid; i < ACT_COMP / 16; i += NTHR)
                cp16(sact + (unsigned)(i * 16), hs + (size_t)i * 16);
            cp_commit();
            for (int i = tid; i < ACT_COMP / 16; i += NTHR)
                cp16(sact + ACT_COMP + (unsigned)(i * 16), hs + ACT_COMP + (size_t)i * 16);
            cp_commit();

            cp_wait<1>(); __syncthreads();           // ĥ_hi landed
#pragma unroll 4
            for (int kc = 0; kc < 16; ++kc) {        // hi x (Whh_hi, Whh_lo)
                unsigned off = kc * 32;
                ldsm4(aAhi + off, ah0,ah1,ah2,ah3);
                ldsm2(aBhh_hi + off, bh0,bh1);
                ldsm2(aBhh_lo + off, bl0,bl1);
                mmabf(c0,c1,c2,c3, ah0,ah1,ah2,ah3, bh0,bh1);
                mmabf(c0,c1,c2,c3, ah0,ah1,ah2,ah3, bl0,bl1);
            }
            cp_wait<0>(); __syncthreads();           // ĥ_lo landed
#pragma unroll 4
            for (int kc = 0; kc < 16; ++kc) {        // lo x Whh_hi
                unsigned off = kc * 32;
                ldsm4(aAlo + off, al0,al1,al2,al3);
                ldsm2(aBhh_hi + off, bh0,bh1);
                mmabf(c0,c1,c2,c3, al0,al1,al2,al3, bh0,bh1);
            }
        }

        // ---- K-half partials ----
        pp[0] = c0; pp[1] = c1; pp[8 * 18] = c2; pp[8 * 18 + 1] = c3;
        __syncthreads();                             // partials ready; actbuf dead

        if (tid < 256) {
            // gate update: one (b, hcl) per thread
            float sv[4];
#pragma unroll
            for (int g = 0; g < 4; ++g) {
                int r = g * 4 + uhcl;
                sv[g] = bias[r] + part[ub * 18 + r] + part[(64 + ub) * 18 + r];
            }
            float ig = sigm(sv[0]);
            float fg = sigm(sv[1]);
            float gv = tanhf(sv[2]);
            float og = sigm(sv[3]);
            float cn = fmaf(fg, cst, ig * gv);
            cst = cn;
            float hn = og * tanhf(cn);

            out[(size_t)t * BATCH * HID + (size_t)ub * HID + hc0 + uhcl] = hn;
            if (t == SEQL - 1)
                out[(size_t)SEQL * BATCH * HID + (size_t)ub * HID + hc0 + uhcl] = hn;

            // split h for the recurrence
            __nv_bfloat16 hh = __float2bfloat16(hn);
            __nv_bfloat16 hl = __float2bfloat16(hn - __bfloat162float(hh));
            __nv_bfloat16* hp = g_hs[t & 1];
            hp[(size_t)ub * APITCH + hc0 + uhcl] = hh;
            hp[(size_t)BATCH * APITCH + (size_t)ub * APITCH + hc0 + uhcl] = hl;

            asm volatile("bar.sync 1, 256;" ::: "memory");
            if (tid == 0) st_rel(&g_flags[cta], F0 + (unsigned)(t + 1));
        } else {
            // warps 8-15: prefetch x̂_{t+1} during update/release
            if (t + 1 < SEQL) {
                const char* gx = (const char*)g_xs + (size_t)(t + 1) * ACT_BYTES;
                for (int i = tid - 256; i < ACT_BYTES / 16; i += 256)
                    cp16(sact + (unsigned)(i * 16), gx + (size_t)i * 16);
                cp_commit();
            }
        }
    }

    // c_n
    if (tid < 256)
        out[(size_t)SEQL * BATCH * HID + (size_t)BATCH * HID
            + (size_t)ub * HID + hc0 + uhcl] = cst;
}

extern "C" void kernel_launch(void* const* d_in, const int* in_sizes, int n_in,
                              void* d_out, int out_size)
{
    const float* input = (const float*)d_in[0];
    const float* Wih   = (const float*)d_in[1];
    const float* Whh   = (const float*)d_in[2];
    const float* bih   = (const float*)d_in[3];
    const float* bhh   = (const float*)d_in[4];
    float* out = (float*)d_out;

    static int configured = 0;
    if (!configured) {
        cudaFuncSetAttribute(lstm_persistent,
                             cudaFuncAttributeMaxDynamicSharedMemorySize, SMEM_TOTAL);
        configured = 1;
    }

    xconv<<<SEQL, 256>>>(input);
    lstm_persistent<<<NCTA, NTHR, SMEM_TOTAL>>>(Wih, Whh, bih, bhh, out);
}

// round 10
// speedup vs baseline: 2.6667x; 1.0141x over previous
#include <cuda_runtime.h>
#include <cuda_bf16.h>
#include <math.h>

#define SEQL   2048
#define BATCH  64
#define INDIM  512
#define HID    512
#define NCTA   128
#define NTHR   512

#define APITCH 520                 // bf16 elems per activation/weight row
#define AROWB  1040                // bytes per row
#define ACT_COMP 66560             // 64 * 1040 (one split component)
#define ACT_BYTES 133120           // hi + lo
#define WREG   16640               // 16 * 1040 (one weight component)

// smem offsets (bytes)
#define ACT_OFF  0
#define W_OFF    133120            // 4 regions: (Wih,hi)(Wih,lo)(Whh,hi)(Whh,lo)
#define P_OFF    199680            // float part[2][64][18]
#define BIAS_OFF 208896            // 16 floats
#define F0_OFF   208960
#define SMEM_TOTAL 208972

__device__ unsigned g_flags[NCTA];                                   // monotonic across runs
__device__ __align__(16) __nv_bfloat16 g_xs[(size_t)SEQL * 2 * BATCH * APITCH];
__device__ __align__(16) __nv_bfloat16 g_hs[2][2 * BATCH * APITCH];  // ping-pong split h

__device__ __forceinline__ float sigm(float x){ return 1.0f/(1.0f+__expf(-x)); }

// ---- cp.async ----
__device__ __forceinline__ void cp16(unsigned s, const void* g){
    asm volatile("cp.async.cg.shared.global [%0], [%1], 16;" :: "r"(s), "l"(g) : "memory");
}
__device__ __forceinline__ void cp_commit(){ asm volatile("cp.async.commit_group;" ::: "memory"); }
template<int N> __device__ __forceinline__ void cp_wait(){
    asm volatile("cp.async.wait_group %0;" :: "n"(N) : "memory");
}

// ---- release/acquire flags ----
__device__ __forceinline__ void st_rel(unsigned* p, unsigned v){
    asm volatile("st.release.gpu.u32 [%0], %1;" :: "l"(p), "r"(v) : "memory");
}
__device__ __forceinline__ unsigned ld_acq(unsigned* p){
    unsigned v; asm volatile("ld.acquire.gpu.u32 %0, [%1];" : "=r"(v) : "l"(p) : "memory");
    return v;
}

// ---- tensor-core primitives ----
__device__ __forceinline__ void ldsm4(unsigned a, unsigned &r0, unsigned &r1,
                                      unsigned &r2, unsigned &r3){
    asm volatile("ldmatrix.sync.aligned.m8n8.x4.shared.b16 {%0,%1,%2,%3}, [%4];"
                 : "=r"(r0), "=r"(r1), "=r"(r2), "=r"(r3) : "r"(a));
}
__device__ __forceinline__ void ldsm2(unsigned a, unsigned &r0, unsigned &r1){
    asm volatile("ldmatrix.sync.aligned.m8n8.x2.shared.b16 {%0,%1}, [%2];"
                 : "=r"(r0), "=r"(r1) : "r"(a));
}
__device__ __forceinline__ void mmabf(float &c0, float &c1, float &c2, float &c3,
                                      unsigned a0, unsigned a1, unsigned a2, unsigned a3,
                                      unsigned b0, unsigned b1){
    asm volatile("mma.sync.aligned.m16n8k16.row.col.f32.bf16.bf16.f32 "
                 "{%0,%1,%2,%3}, {%4,%5,%6,%7}, {%8,%9}, {%0,%1,%2,%3};"
                 : "+f"(c0), "+f"(c1), "+f"(c2), "+f"(c3)
                 : "r"(a0), "r"(a1), "r"(a2), "r"(a3), "r"(b0), "r"(b1));
}

// ============ conversion kernel: input fp32 -> split bf16 tiles ============
__global__ void __launch_bounds__(256, 4)
xconv(const float* __restrict__ in)
{
    int t = blockIdx.x;
    const float2* src = (const float2*)(in + (size_t)t * BATCH * INDIM);
    __nv_bfloat16* dhi = g_xs + (size_t)t * 2 * BATCH * APITCH;
    __nv_bfloat16* dlo = dhi + BATCH * APITCH;
    for (int i = threadIdx.x; i < BATCH * INDIM / 2; i += 256) {
        int b = i >> 8, kk = i & 255;
        float2 v = src[(size_t)b * 256 + kk];
        __nv_bfloat16 h0 = __float2bfloat16(v.x);
        __nv_bfloat16 h1 = __float2bfloat16(v.y);
        __nv_bfloat162 hp; hp.x = h0; hp.y = h1;
        __nv_bfloat162 lp;
        lp.x = __float2bfloat16(v.x - __bfloat162float(h0));
        lp.y = __float2bfloat16(v.y - __bfloat162float(h1));
        ((__nv_bfloat162*)(dhi + b * APITCH))[kk] = hp;
        ((__nv_bfloat162*)(dlo + b * APITCH))[kk] = lp;
    }
}

// ============ persistent LSTM kernel ============
__global__ void __launch_bounds__(NTHR, 1)
lstm_persistent(const float* __restrict__ Wih,
                const float* __restrict__ Whh,
                const float* __restrict__ bih,
                const float* __restrict__ bhh,
                float* __restrict__ out)
{
    extern __shared__ char smem[];
    const unsigned sbase = (unsigned)__cvta_generic_to_shared(smem);
    const unsigned sact  = sbase + ACT_OFF;
    const unsigned swb   = sbase + W_OFF;
    float* part = (float*)(smem + P_OFF);           // [2][64][18]
    float* bias = (float*)(smem + BIAS_OFF);        // 16
    unsigned* sF0 = (unsigned*)(smem + F0_OFF);

    const int tid = threadIdx.x;
    const int cta = blockIdx.x;
    const int hc0 = cta * 4;

    if (tid == 0) *sF0 = g_flags[cta];

    // ---- convert this CTA's weight slices to split bf16 in smem ----
    for (int i = tid; i < 16 * 512; i += NTHR) {
        int r = i >> 9, k = i & 511;
        int grow = (r >> 2) * HID + hc0 + (r & 3);
        float wv = Wih[(size_t)grow * INDIM + k];
        __nv_bfloat16 h = __float2bfloat16(wv);
        *(__nv_bfloat16*)(smem + W_OFF + 0*WREG + r*AROWB + k*2) = h;
        *(__nv_bfloat16*)(smem + W_OFF + 1*WREG + r*AROWB + k*2) =
            __float2bfloat16(wv - __bfloat162float(h));
        wv = Whh[(size_t)grow * HID + k];
        h = __float2bfloat16(wv);
        *(__nv_bfloat16*)(smem + W_OFF + 2*WREG + r*AROWB + k*2) = h;
        *(__nv_bfloat16*)(smem + W_OFF + 3*WREG + r*AROWB + k*2) =
            __float2bfloat16(wv - __bfloat162float(h));
    }
    if (tid < 16) {
        int grow = (tid >> 2) * HID + hc0 + (tid & 3);
        bias[tid] = bih[grow] + bhh[grow];
    }

    // ---- MMA warp identity: 16 warps = mt(4) x nt(2) x kh(2) ----
    const int wid  = tid >> 5;
    const int lane = tid & 31;
    const int mt   = wid & 3;
    const int nt   = (wid >> 2) & 1;
    const int kh   = (wid >> 3) & 1;
    const int kb   = kh * 256;                       // k offset (elems)

    const int arow = mt * 16 + (lane & 15);
    const int acol = (lane >> 4) * 8;
    const unsigned aAhi = sact + (unsigned)(arow * AROWB + (kb + acol) * 2);
    const unsigned aAlo = aAhi + ACT_COMP;

    const int brow = nt * 8 + (lane & 7);
    const int bcol = ((lane >> 3) & 1) * 8;
    const unsigned bOff = (unsigned)(brow * AROWB + (kb + bcol) * 2);
    const unsigned aBih_hi = swb + 0*WREG + bOff;
    const unsigned aBih_lo = swb + 1*WREG + bOff;
    const unsigned aBhh_hi = swb + 2*WREG + bOff;
    const unsigned aBhh_lo = swb + 3*WREG + bOff;

    // partial store position
    const int prow = mt * 16 + (lane >> 2);
    const int pcol = nt * 8 + (lane & 3) * 2;
    float* pp = part + (size_t)((kh * 64 + prow) * 18 + pcol);

    // update identity (threads 0..255): one (b, hcl) output per thread
    const int ub   = tid >> 2;
    const int uhcl = tid & 3;

    float cst = 0.0f;

    // ---- prefetch x̂_0 ----
    {
        const char* gx0 = (const char*)g_xs;
        for (int i = tid; i < ACT_BYTES / 16; i += NTHR)
            cp16(sact + (unsigned)(i * 16), gx0 + (size_t)i * 16);
        cp_commit();
    }
    __syncthreads();
    const unsigned F0 = *sF0;

    // ---- hoist static Whh b-fragments (hi + lo) into registers ----
    unsigned bhh0[16], bhh1[16], bhl0[16], bhl1[16];
#pragma unroll
    for (int kc = 0; kc < 16; ++kc) {
        ldsm2(aBhh_hi + kc * 32, bhh0[kc], bhh1[kc]);
        ldsm2(aBhh_lo + kc * 32, bhl0[kc], bhl1[kc]);
    }

    for (int t = 0; t < SEQL; ++t) {
        cp_wait<0>(); __syncthreads();               // x̂_t staged

        float c0 = 0.f, c1 = 0.f, c2 = 0.f, c3 = 0.f;
        unsigned ah0,ah1,ah2,ah3, al0,al1,al2,al3, bh0,bh1, bl0,bl1;

        // ---- x-GEMM chunks 0..7 (region A of x consumed after this) ----
#pragma unroll 4
        for (int kc = 0; kc < 8; ++kc) {
            unsigned off = kc * 32;
            ldsm4(aAhi + off, ah0,ah1,ah2,ah3);
            ldsm4(aAlo + off, al0,al1,al2,al3);
            ldsm2(aBih_hi + off, bh0,bh1);
            ldsm2(aBih_lo + off, bl0,bl1);
            mmabf(c0,c1,c2,c3, ah0,ah1,ah2,ah3, bh0,bh1);
            mmabf(c0,c1,c2,c3, al0,al1,al2,al3, bh0,bh1);
            mmabf(c0,c1,c2,c3, ah0,ah1,ah2,ah3, bl0,bl1);
        }

        if (t > 0) {
            // ---- distributed poll: warp w checks flags[w*8 .. w*8+7] ----
            {
                unsigned tgt = F0 + (unsigned)t;
                unsigned* fp = &g_flags[(wid << 3) + (lane & 7)];
                for (;;) {
                    unsigned f = ld_acq(fp);
                    if (__all_sync(0xffffffffu, (int)(f - tgt) >= 0)) break;
                }
            }
            __syncthreads();                         // all flags seen; region A dead

            // ---- stage ĥ region A: cols [0,128)∪[256,384), hi+lo ----
            {
                const char* hs = (const char*)g_hs[(t - 1) & 1];
#pragma unroll
                for (int j = 0; j < 8; ++j) {
                    int i = tid + j * NTHR;          // 0..4095
                    int comp = i >> 11, r = (i >> 5) & 63, u = i & 31;
                    unsigned colb = (u < 16) ? (unsigned)(u * 16)
                                             : (unsigned)(512 + (u - 16) * 16);
                    unsigned off = (unsigned)(comp * ACT_COMP + r * AROWB) + colb;
                    cp16(sact + off, hs + off);
                }
                cp_commit();
            }

            // ---- x-GEMM chunks 8..15 (covers region-A flight) ----
#pragma unroll 4
            for (int kc = 8; kc < 16; ++kc) {
                unsigned off = kc * 32;
                ldsm4(aAhi + off, ah0,ah1,ah2,ah3);
                ldsm4(aAlo + off, al0,al1,al2,al3);
                ldsm2(aBih_hi + off, bh0,bh1);
                ldsm2(aBih_lo + off, bl0,bl1);
                mmabf(c0,c1,c2,c3, ah0,ah1,ah2,ah3, bh0,bh1);
                mmabf(c0,c1,c2,c3, al0,al1,al2,al3, bh0,bh1);
                mmabf(c0,c1,c2,c3, ah0,ah1,ah2,ah3, bl0,bl1);
            }
            __syncthreads();                         // region B of x dead

            // ---- stage ĥ region B: cols [128,256)∪[384,512) ----
            {
                const char* hs = (const char*)g_hs[(t - 1) & 1];
#pragma unroll
                for (int j = 0; j < 8; ++j) {
                    int i = tid + j * NTHR;
                    int comp = i >> 11, r = (i >> 5) & 63, u = i & 31;
                    unsigned colb = 256u + ((u < 16) ? (unsigned)(u * 16)
                                                     : (unsigned)(512 + (u - 16) * 16));
                    unsigned off = (unsigned)(comp * ACT_COMP + r * AROWB) + colb;
                    cp16(sact + off, hs + off);
                }
                cp_commit();
            }

            cp_wait<1>(); __syncthreads();           // ĥ region A landed
#pragma unroll 4
            for (int kc = 0; kc < 8; ++kc) {         // h-MMA region A (b from regs)
                unsigned off = kc * 32;
                ldsm4(aAhi + off, ah0,ah1,ah2,ah3);
                ldsm4(aAlo + off, al0,al1,al2,al3);
                mmabf(c0,c1,c2,c3, ah0,ah1,ah2,ah3, bhh0[kc],bhh1[kc]);
                mmabf(c0,c1,c2,c3, ah0,ah1,ah2,ah3, bhl0[kc],bhl1[kc]);
                mmabf(c0,c1,c2,c3, al0,al1,al2,al3, bhh0[kc],bhh1[kc]);
            }
            cp_wait<0>(); __syncthreads();           // ĥ region B landed
#pragma unroll 4
            for (int kc = 8; kc < 16; ++kc) {        // h-MMA region B
                unsigned off = kc * 32;
                ldsm4(aAhi + off, ah0,ah1,ah2,ah3);
                ldsm4(aAlo + off, al0,al1,al2,al3);
                mmabf(c0,c1,c2,c3, ah0,ah1,ah2,ah3, bhh0[kc],bhh1[kc]);
                mmabf(c0,c1,c2,c3, ah0,ah1,ah2,ah3, bhl0[kc],bhl1[kc]);
                mmabf(c0,c1,c2,c3, al0,al1,al2,al3, bhh0[kc],bhh1[kc]);
            }
        } else {
            // t == 0: finish x-GEMM only
#pragma unroll 4
            for (int kc = 8; kc < 16; ++kc) {
                unsigned off = kc * 32;
                ldsm4(aAhi + off, ah0,ah1,ah2,ah3);
                ldsm4(aAlo + off, al0,al1,al2,al3);
                ldsm2(aBih_hi + off, bh0,bh1);
                ldsm2(aBih_lo + off, bl0,bl1);
                mmabf(c0,c1,c2,c3, ah0,ah1,ah2,ah3, bh0,bh1);
                mmabf(c0,c1,c2,c3, al0,al1,al2,al3, bh0,bh1);
                mmabf(c0,c1,c2,c3, ah0,ah1,ah2,ah3, bl0,bl1);
            }
        }

        // ---- K-half partials ----
        pp[0] = c0; pp[1] = c1; pp[8 * 18] = c2; pp[8 * 18 + 1] = c3;
        __syncthreads();                             // partials ready; act buffer dead

        if (tid < 256) {
            // gate update: one (b, hcl) per thread
            float sv[4];
#pragma unroll
            for (int g = 0; g < 4; ++g) {
                int r = g * 4 + uhcl;
                sv[g] = bias[r] + part[ub * 18 + r] + part[(64 + ub) * 18 + r];
            }
            float ig = sigm(sv[0]);
            float fg = sigm(sv[1]);
            float gv = tanhf(sv[2]);
            float og = sigm(sv[3]);
            float cn = fmaf(fg, cst, ig * gv);
            cst = cn;
            float hn = og * tanhf(cn);

            out[(size_t)t * BATCH * HID + (size_t)ub * HID + hc0 + uhcl] = hn;
            if (t == SEQL - 1)
                out[(size_t)SEQL * BATCH * HID + (size_t)ub * HID + hc0 + uhcl] = hn;

            // split h for the recurrence
            __nv_bfloat16 hh = __float2bfloat16(hn);
            __nv_bfloat16 hl = __float2bfloat16(hn - __bfloat162float(hh));
            __nv_bfloat16* hp = g_hs[t & 1];
            hp[(size_t)ub * APITCH + hc0 + uhcl] = hh;
            hp[(size_t)BATCH * APITCH + (size_t)ub * APITCH + hc0 + uhcl] = hl;

            asm volatile("bar.sync 1, 256;" ::: "memory");
            if (tid == 0) st_rel(&g_flags[cta], F0 + (unsigned)(t + 1));
        } else {
            // warps 8-15: prefetch x̂_{t+1} during update/release
            if (t + 1 < SEQL) {
                const char* gx = (const char*)g_xs + (size_t)(t + 1) * ACT_BYTES;
                for (int i = tid - 256; i < ACT_BYTES / 16; i += 256)
                    cp16(sact + (unsigned)(i * 16), gx + (size_t)i * 16);
                cp_commit();
            }
        }
    }

    // c_n
    if (tid < 256)
        out[(size_t)SEQL * BATCH * HID + (size_t)BATCH * HID
            + (size_t)ub * HID + hc0 + uhcl] = cst;
}

extern "C" void kernel_launch(void* const* d_in, const int* in_sizes, int n_in,
                              void* d_out, int out_size)
{
    const float* input = (const float*)d_in[0];
    const float* Wih   = (const float*)d_in[1];
    const float* Whh   = (const float*)d_in[2];
    const float* bih   = (const float*)d_in[3];
    const float* bhh   = (const float*)d_in[4];
    float* out = (float*)d_out;

    static int configured = 0;
    if (!configured) {
        cudaFuncSetAttribute(lstm_persistent,
                             cudaFuncAttributeMaxDynamicSharedMemorySize, SMEM_TOTAL);
        configured = 1;
    }

    xconv<<<SEQL, 256>>>(input);
    lstm_persistent<<<NCTA, NTHR, SMEM_TOTAL>>>(Wih, Whh, bih, bhh, out);
}